// round 6
// baseline (speedup 1.0000x reference)
#include <cuda_runtime.h>
#include <cuda_bf16.h>
#include <cstdint>

#define NN 100000
#define EE 260000
#define DD 300
#define D4 75          // DD/4
#define LL 5
#define GG 4096
#define BN_EPS 1e-5f

// ---- HMMA GEMM geometry ----
#define BM   128       // block M tile
#define BNB  64        // block N tile
#define BKC  64        // K chunk per smem stage
#define KPAD 320       // padded K (5 chunks)
#define NPAD 320       // padded N (5 blocks of 64)
#define NCHK 5
#define NMAT 13

// smem stage layout (bytes): A hi | A lo | B hi | B lo
#define SA_H 0
#define SA_L 16384
#define SB_H 32768
#define SB_L 40960
#define STAGE 49152
#define SMEMSZ (2 * STAGE)   // 96 KB dynamic

// ---------------- scratch (device globals; no allocation allowed) ----------
__device__ __align__(16) float g_h  [(size_t)NN * DD];
__device__ __align__(16) float g_e  [(size_t)EE * DD];
__device__ __align__(16) float g_agg[(size_t)NN * DD];
__device__ __align__(16) float g_tmp[(size_t)NN * DD];
__device__ __align__(16) float g_out[(size_t)NN * DD];
__device__             float g_stats[2 * DD];
__device__ __align__(16) float g_pool[(size_t)GG * DD];
__device__             float g_cnt [GG];
// preconverted weights: [NMAT][NPAD rows(n)][KPAD cols(k)] bf16, hi and lo planes
__device__ __align__(16) __nv_bfloat16 g_wbh[(size_t)NMAT * NPAD * KPAD];
__device__ __align__(16) __nv_bfloat16 g_wbl[(size_t)NMAT * NPAD * KPAD];

// ---------------- helpers ----------------------------------------------------
__device__ __forceinline__ uint32_t smem_u32(const void* p) {
    uint32_t a;
    asm("{ .reg .u64 t; cvta.to.shared.u64 t, %1; cvt.u32.u64 %0, t; }" : "=r"(a) : "l"(p));
    return a;
}
__device__ __forceinline__ uint32_t swz(uint32_t off) { return off ^ ((off >> 3) & 0x70); }

__device__ __forceinline__ void ldsm4(uint32_t* r, uint32_t addr) {
    asm volatile("ldmatrix.sync.aligned.m8n8.x4.shared.b16 {%0,%1,%2,%3}, [%4];"
                 : "=r"(r[0]), "=r"(r[1]), "=r"(r[2]), "=r"(r[3]) : "r"(addr));
}
__device__ __forceinline__ void mma_bf16(float* d, const uint32_t* a, const uint32_t* b) {
    asm volatile(
        "mma.sync.aligned.m16n8k16.row.col.f32.bf16.bf16.f32 "
        "{%0,%1,%2,%3}, {%4,%5,%6,%7}, {%8,%9}, {%0,%1,%2,%3};"
        : "+f"(d[0]), "+f"(d[1]), "+f"(d[2]), "+f"(d[3])
        : "r"(a[0]), "r"(a[1]), "r"(a[2]), "r"(a[3]), "r"(b[0]), "r"(b[1]));
}
__device__ __forceinline__ uint32_t pack_bf16(float a, float b) {
    __nv_bfloat16 ha = __float2bfloat16_rn(a), hb = __float2bfloat16_rn(b);
    return (uint32_t)__bfloat16_as_ushort(ha) | ((uint32_t)__bfloat16_as_ushort(hb) << 16);
}

// ---------------- weight preconversion (13 mats -> bf16 hi/lo, [n][k], padded)
__global__ void wprep_k(const float* __restrict__ nap_w2, const float* __restrict__ ee_w2,
                        const float* __restrict__ mlp_w1, const float* __restrict__ mlp_w2,
                        const float* __restrict__ pool_w) {
    int idx = blockIdx.x * blockDim.x + threadIdx.x;
    if (idx >= NMAT * NPAD * KPAD) return;
    int mat = idx / (NPAD * KPAD);
    int rem = idx - mat * (NPAD * KPAD);
    int n = rem / KPAD, k = rem - n * KPAD;
    const float* W;
    if (mat == 0)      W = nap_w2;
    else if (mat == 1) W = ee_w2;
    else if (mat < 7)  W = mlp_w1 + (size_t)(mat - 2) * DD * DD;
    else if (mat < 12) W = mlp_w2 + (size_t)(mat - 7) * DD * DD;
    else               W = pool_w;
    float v = (n < DD && k < DD) ? W[(size_t)k * DD + n] : 0.f;
    __nv_bfloat16 hi = __float2bfloat16_rn(v);
    __nv_bfloat16 lo = __float2bfloat16_rn(v - __bfloat162float(hi));
    g_wbh[idx] = hi;
    g_wbl[idx] = lo;
}

// ---------------- HMMA GEMM -------------------------------------------------
// MODE 0: A read from memory.  MODE 1: A = relu(chi*w1[0]+fc*w1[1]+b1) on the fly.
// MODE 2: A = relu(ea0*w1[0]+ea1*w1[1]+ea2*w1[2]+b1) on the fly.
// stats!=0: accumulate per-column sum/sumsq of C into g_stats (for BN).
template<int MODE>
__global__ __launch_bounds__(256, 2)
void hgemm_k(const float* __restrict__ A,
             const float* __restrict__ p0, const float* __restrict__ p1,
             const float* __restrict__ pw1, const float* __restrict__ pb1,
             const __nv_bfloat16* __restrict__ Bh, const __nv_bfloat16* __restrict__ Bl,
             const float* __restrict__ bias, float* __restrict__ C,
             float* __restrict__ C2, int M, int relu, int stats,
             const float* __restrict__ gtab, const int* __restrict__ gidx) {
    extern __shared__ char smem[];
    __shared__ float sred[128];
    const uint32_t sb = smem_u32(smem);
    const int tid  = threadIdx.x;
    const int lane = tid & 31;
    const int wid  = tid >> 5;
    const int warpM = wid & 3;        // 4 warps over M (32 rows each)
    const int warpN = wid >> 2;       // 2 warps over N (32 cols each)
    const int m0 = blockIdx.y * BM;
    const int n0 = blockIdx.x * BNB;

    // per-row scalars for fused first-layer projection
    const int ar   = tid >> 1;
    const int half = tid & 1;
    const int gm_a = m0 + ar;
    float pr0 = 0.f, pr1 = 0.f, pr2 = 0.f;
    if constexpr (MODE == 1) {
        if (gm_a < M) { pr0 = p0[gm_a]; pr1 = p1[gm_a]; }
    } else if constexpr (MODE == 2) {
        if (gm_a < M) { pr0 = p0[gm_a * 3]; pr1 = p0[gm_a * 3 + 1]; pr2 = p0[gm_a * 3 + 2]; }
    }

    auto fill = [&](int c, int s) {
        char* st = smem + (s ? STAGE : 0);
        // A: 128 rows x 64 k (computed or loaded, converted to bf16 hi/lo)
        {
            const float* arow = (MODE == 0) ? A + (size_t)gm_a * DD + c * BKC : nullptr;
            #pragma unroll
            for (int i = 0; i < 8; i++) {
                const int kl = half * 32 + i * 4;
                const int k  = c * BKC + kl;
                float4 v = make_float4(0.f, 0.f, 0.f, 0.f);
                if (gm_a < M && k + 4 <= DD) {
                    if constexpr (MODE == 0) {
                        v = *(const float4*)&arow[kl];
                    } else {
                        float4 w0 = *(const float4*)&pw1[k];
                        float4 w1r = *(const float4*)&pw1[DD + k];
                        float4 b  = *(const float4*)&pb1[k];
                        if constexpr (MODE == 1) {
                            v.x = fmaxf(pr0 * w0.x + pr1 * w1r.x + b.x, 0.f);
                            v.y = fmaxf(pr0 * w0.y + pr1 * w1r.y + b.y, 0.f);
                            v.z = fmaxf(pr0 * w0.z + pr1 * w1r.z + b.z, 0.f);
                            v.w = fmaxf(pr0 * w0.w + pr1 * w1r.w + b.w, 0.f);
                        } else {
                            float4 w2r = *(const float4*)&pw1[2 * DD + k];
                            v.x = fmaxf(pr0 * w0.x + pr1 * w1r.x + pr2 * w2r.x + b.x, 0.f);
                            v.y = fmaxf(pr0 * w0.y + pr1 * w1r.y + pr2 * w2r.y + b.y, 0.f);
                            v.z = fmaxf(pr0 * w0.z + pr1 * w1r.z + pr2 * w2r.z + b.z, 0.f);
                            v.w = fmaxf(pr0 * w0.w + pr1 * w1r.w + pr2 * w2r.w + b.w, 0.f);
                        }
                    }
                }
                float hx = __bfloat162float(__float2bfloat16_rn(v.x));
                float hy = __bfloat162float(__float2bfloat16_rn(v.y));
                float hz = __bfloat162float(__float2bfloat16_rn(v.z));
                float hw = __bfloat162float(__float2bfloat16_rn(v.w));
                uint32_t hA = pack_bf16(v.x, v.y), hB = pack_bf16(v.z, v.w);
                uint32_t lA = pack_bf16(v.x - hx, v.y - hy), lB = pack_bf16(v.z - hz, v.w - hw);
                const uint32_t so = swz(ar * 128 + kl * 2);
                *(uint2*)(st + SA_H + so) = make_uint2(hA, hB);
                *(uint2*)(st + SA_L + so) = make_uint2(lA, lB);
            }
        }
        // B: 64 n-rows x 64 k (bf16 preconverted, padded -> no guards)
        {
            #pragma unroll
            for (int it = 0; it < 2; it++) {
                const int i = tid + it * 256;     // < 512
                const int n = i >> 3, ku = i & 7;
                const size_t go = (size_t)(n0 + n) * KPAD + c * BKC + ku * 8;
                uint4 vh = *(const uint4*)(Bh + go);
                uint4 vl = *(const uint4*)(Bl + go);
                const uint32_t so = swz(n * 128 + ku * 16);
                *(uint4*)(st + SB_H + so) = vh;
                *(uint4*)(st + SB_L + so) = vl;
            }
        }
    };

    float acc[2][4][4] = {};

    // ldmatrix lane geometry
    const int a_row = lane & 15;
    const int a_kc  = (lane >> 4) * 8;
    const int b_row = (lane & 7) + ((lane & 16) ? 8 : 0);
    const int b_kc  = (lane & 8);

    fill(0, 0);
    __syncthreads();

    for (int c = 0; c < NCHK; c++) {
        const int s = c & 1;
        if (c + 1 < NCHK) fill(c + 1, s ^ 1);

        const uint32_t stb = sb + (s ? STAGE : 0);
        #pragma unroll
        for (int ks = 0; ks < 4; ks++) {
            const int k0 = ks * 16;
            uint32_t ah[2][4], al[2][4], bh[2][4], bl[2][4];
            #pragma unroll
            for (int mt = 0; mt < 2; mt++) {
                const uint32_t off = swz((warpM * 32 + mt * 16 + a_row) * 128 + (k0 + a_kc) * 2);
                ldsm4(ah[mt], stb + SA_H + off);
                ldsm4(al[mt], stb + SA_L + off);
            }
            #pragma unroll
            for (int g = 0; g < 2; g++) {
                const uint32_t off = swz((warpN * 32 + g * 16 + b_row) * 128 + (k0 + b_kc) * 2);
                ldsm4(bh[g], stb + SB_H + off);
                ldsm4(bl[g], stb + SB_L + off);
            }
            #pragma unroll
            for (int mt = 0; mt < 2; mt++) {
                #pragma unroll
                for (int nt = 0; nt < 4; nt++) {
                    const int g = nt >> 1, o = (nt & 1) * 2;
                    mma_bf16(acc[mt][nt], ah[mt], &bh[g][o]);
                    mma_bf16(acc[mt][nt], ah[mt], &bl[g][o]);
                    mma_bf16(acc[mt][nt], al[mt], &bh[g][o]);
                }
            }
        }
        __syncthreads();
    }

    // ---- epilogue: bias + optional gather + relu, dual-write, optional BN stats
    const int er = lane >> 2;
    const int ec = (lane & 3) * 2;
    float cs[8] = {}, cq[8] = {};
    #pragma unroll
    for (int mt = 0; mt < 2; mt++) {
        #pragma unroll
        for (int rr = 0; rr < 2; rr++) {
            const int gm = m0 + warpM * 32 + mt * 16 + rr * 8 + er;
            if (gm < M) {
                const float* grow = (gtab != nullptr) ? gtab + (size_t)gidx[gm] * DD : nullptr;
                float* crow  = C + (size_t)gm * DD;
                float* c2row = (C2 != nullptr) ? C2 + (size_t)gm * DD : nullptr;
                #pragma unroll
                for (int nt = 0; nt < 4; nt++) {
                    const int n = n0 + warpN * 32 + nt * 8 + ec;
                    if (n + 2 <= DD) {
                        float v0 = acc[mt][nt][rr * 2 + 0] + bias[n];
                        float v1 = acc[mt][nt][rr * 2 + 1] + bias[n + 1];
                        if (grow != nullptr) { v0 += grow[n]; v1 += grow[n + 1]; }
                        if (relu) { v0 = fmaxf(v0, 0.f); v1 = fmaxf(v1, 0.f); }
                        *(float2*)&crow[n] = make_float2(v0, v1);
                        if (c2row != nullptr) *(float2*)&c2row[n] = make_float2(v0, v1);
                        if (stats) {
                            const int j = nt * 2;
                            cs[j] += v0; cq[j] += v0 * v0;
                            cs[j + 1] += v1; cq[j + 1] += v1 * v1;
                        }
                    }
                }
            }
        }
    }
    if (stats) {
        if (tid < 64) { sred[tid] = 0.f; sred[64 + tid] = 0.f; }
        __syncthreads();
        #pragma unroll
        for (int nt = 0; nt < 4; nt++) {
            const int col = warpN * 32 + nt * 8 + ec;
            atomicAdd(&sred[col],       cs[nt * 2]);
            atomicAdd(&sred[64 + col],  cq[nt * 2]);
            atomicAdd(&sred[col + 1],      cs[nt * 2 + 1]);
            atomicAdd(&sred[64 + col + 1], cq[nt * 2 + 1]);
        }
        __syncthreads();
        if (tid < 64) {
            const int n = n0 + tid;
            if (n < DD) {
                atomicAdd(&g_stats[n],      sred[tid]);
                atomicAdd(&g_stats[DD + n], sred[64 + tid]);
            }
        }
    }
}

// ---------------- message + scatter-add (agg preloaded with h) --------------
// 16 threads per edge, j-stride loop over 75 float4 groups.
__global__ void msg_k(const int* __restrict__ ei) {
    int idx = blockIdx.x * blockDim.x + threadIdx.x;
    if (idx >= EE * 16) return;
    int e = idx >> 4, t = idx & 15;
    int s = __ldg(&ei[e]);
    int d = __ldg(&ei[EE + e]);
    const float4* hrow = reinterpret_cast<const float4*>(g_h) + (size_t)s * D4;
    const float4* erow = reinterpret_cast<const float4*>(g_e) + (size_t)e * D4;
    float* arow = &g_agg[(size_t)d * DD];
    #pragma unroll 5
    for (int j = t; j < D4; j += 16) {
        float4 hv = hrow[j];
        float4 ev = erow[j];
        float* base = arow + j * 4;
        atomicAdd(base + 0, fmaxf(hv.x + ev.x, 0.f));
        atomicAdd(base + 1, fmaxf(hv.y + ev.y, 0.f));
        atomicAdd(base + 2, fmaxf(hv.z + ev.z, 0.f));
        atomicAdd(base + 3, fmaxf(hv.w + ev.w, 0.f));
    }
}

// ---------------- batchnorm --------------------------------------------------
__global__ void zero_stats_k() {
    int i = threadIdx.x;
    if (i < 2 * DD) g_stats[i] = 0.f;
}

__global__ void bn_apply_k(const float* __restrict__ gamma, const float* __restrict__ beta) {
    int idx = blockIdx.x * blockDim.x + threadIdx.x;
    if (idx >= NN * D4) return;
    int j = idx % D4;
    int d = j * 4;
    const float invN = 1.f / (float)NN;
    float4 mu = make_float4(g_stats[d] * invN, g_stats[d + 1] * invN,
                            g_stats[d + 2] * invN, g_stats[d + 3] * invN);
    float4 ms = make_float4(g_stats[DD + d] * invN, g_stats[DD + d + 1] * invN,
                            g_stats[DD + d + 2] * invN, g_stats[DD + d + 3] * invN);
    float4 ga = *(const float4*)&gamma[d];
    float4 be = *(const float4*)&beta[d];
    float4 o = reinterpret_cast<const float4*>(g_out)[idx];
    float4 v;
    v.x = fmaxf(ga.x * (o.x - mu.x) * rsqrtf(ms.x - mu.x * mu.x + BN_EPS) + be.x, 0.f);
    v.y = fmaxf(ga.y * (o.y - mu.y) * rsqrtf(ms.y - mu.y * mu.y + BN_EPS) + be.y, 0.f);
    v.z = fmaxf(ga.z * (o.z - mu.z) * rsqrtf(ms.z - mu.z * mu.z + BN_EPS) + be.z, 0.f);
    v.w = fmaxf(ga.w * (o.w - mu.w) * rsqrtf(ms.w - mu.w * mu.w + BN_EPS) + be.w, 0.f);
    reinterpret_cast<float4*>(g_h)[idx]   = v;
    reinterpret_cast<float4*>(g_agg)[idx] = v;   // pre-seed next layer aggregate
}

// ---------------- pooling ----------------------------------------------------
__global__ void pool_zero_k() {
    int idx = blockIdx.x * blockDim.x + threadIdx.x;
    if (idx < GG * DD) g_pool[idx] = 0.f;
    if (idx < GG) g_cnt[idx] = 0.f;
}

__global__ void pool_acc_k(const int* __restrict__ batch) {
    int idx = blockIdx.x * blockDim.x + threadIdx.x;
    if (idx >= NN * D4) return;
    int n = idx / D4, j = idx - n * D4;
    int g = batch[n];
    float4 v = reinterpret_cast<const float4*>(g_h)[(size_t)n * D4 + j];
    float* base = &g_pool[(size_t)g * DD + j * 4];
    atomicAdd(base + 0, v.x);
    atomicAdd(base + 1, v.y);
    atomicAdd(base + 2, v.z);
    atomicAdd(base + 3, v.w);
}

__global__ void pool_cnt_k(const int* __restrict__ batch) {
    int n = blockIdx.x * blockDim.x + threadIdx.x;
    if (n >= NN) return;
    atomicAdd(&g_cnt[batch[n]], 1.f);
}

__global__ void pool_div_k() {
    int idx = blockIdx.x * blockDim.x + threadIdx.x;
    if (idx >= GG * DD) return;
    int g = idx / DD;
    float c = g_cnt[g];
    g_pool[idx] = (c > 0.f) ? g_pool[idx] / c : 0.f;
}

// ---------------- launch -----------------------------------------------------
static inline int cdiv(int a, int b) { return (a + b - 1) / b; }

extern "C" void kernel_launch(void* const* d_in, const int* in_sizes, int n_in,
                              void* d_out, int out_size) {
    const int*   z        = (const int*)  d_in[0];
    const float* chi      = (const float*)d_in[1];
    const float* fc       = (const float*)d_in[2];
    const int*   ei       = (const int*)  d_in[3];
    const float* ea       = (const float*)d_in[4];
    const int*   batch    = (const int*)  d_in[5];
    const float* atom_emb = (const float*)d_in[6];
    const float* nap_w1   = (const float*)d_in[7];
    const float* nap_b1   = (const float*)d_in[8];
    const float* nap_w2   = (const float*)d_in[9];
    const float* nap_b2   = (const float*)d_in[10];
    const float* ee_w1    = (const float*)d_in[11];
    const float* ee_b1    = (const float*)d_in[12];
    const float* ee_w2    = (const float*)d_in[13];
    const float* ee_b2    = (const float*)d_in[14];
    const float* mlp_w1   = (const float*)d_in[15];
    const float* mlp_b1   = (const float*)d_in[16];
    const float* mlp_w2   = (const float*)d_in[17];
    const float* mlp_b2   = (const float*)d_in[18];
    const float* bn_gamma = (const float*)d_in[19];
    const float* bn_beta  = (const float*)d_in[20];
    const float* pool_w   = (const float*)d_in[21];
    const float* pool_b   = (const float*)d_in[22];
    float* out = (float*)d_out;

    float *ph, *pe, *pagg, *ptmp, *pout, *ppool;
    __nv_bfloat16 *pwh, *pwl;
    cudaGetSymbolAddress((void**)&ph,    g_h);
    cudaGetSymbolAddress((void**)&pe,    g_e);
    cudaGetSymbolAddress((void**)&pagg,  g_agg);
    cudaGetSymbolAddress((void**)&ptmp,  g_tmp);
    cudaGetSymbolAddress((void**)&pout,  g_out);
    cudaGetSymbolAddress((void**)&ppool, g_pool);
    cudaGetSymbolAddress((void**)&pwh,   g_wbh);
    cudaGetSymbolAddress((void**)&pwl,   g_wbl);

    cudaFuncSetAttribute(hgemm_k<0>, cudaFuncAttributeMaxDynamicSharedMemorySize, SMEMSZ);
    cudaFuncSetAttribute(hgemm_k<1>, cudaFuncAttributeMaxDynamicSharedMemorySize, SMEMSZ);
    cudaFuncSetAttribute(hgemm_k<2>, cudaFuncAttributeMaxDynamicSharedMemorySize, SMEMSZ);

    const int TPB = 256;
    const size_t WSTRIDE = (size_t)NPAD * KPAD;
    #define WH(m) (pwh + (size_t)(m) * WSTRIDE)
    #define WL(m) (pwl + (size_t)(m) * WSTRIDE)

    dim3 grid_N(NPAD / BNB, cdiv(NN, BM));
    dim3 grid_E(NPAD / BNB, cdiv(EE, BM));
    dim3 grid_G(NPAD / BNB, cdiv(GG, BM));

    // ---- preconvert all weight matrices to bf16 hi/lo (K-major, padded)
    wprep_k<<<cdiv(NMAT * NPAD * KPAD, TPB), TPB>>>(nap_w2, ee_w2, mlp_w1, mlp_w2, pool_w);

    // ---- node features: h0 = atom_emb[z] + MLP(node_attr); seed agg = h0 (fused pre)
    hgemm_k<1><<<grid_N, 256, SMEMSZ>>>(nullptr, chi, fc, nap_w1, nap_b1,
                                        WH(0), WL(0), nap_b2, ph, pagg, NN, 0, 0, atom_emb, z);

    // ---- edge features: e = MLP(edge_attr) (fused pre)
    hgemm_k<2><<<grid_E, 256, SMEMSZ>>>(nullptr, ea, nullptr, ee_w1, ee_b1,
                                        WH(1), WL(1), ee_b2, pe, nullptr, EE, 0, 0, nullptr, nullptr);

    // ---- L GINE layers
    for (int l = 0; l < LL; l++) {
        msg_k<<<cdiv(EE * 16, TPB), TPB>>>(ei);
        hgemm_k<0><<<grid_N, 256, SMEMSZ>>>(pagg, nullptr, nullptr, nullptr, nullptr,
                                            WH(2 + l), WL(2 + l), mlp_b1 + l * DD,
                                            ptmp, nullptr, NN, 1, 0, nullptr, nullptr);
        zero_stats_k<<<1, 2 * DD>>>();
        hgemm_k<0><<<grid_N, 256, SMEMSZ>>>(ptmp, nullptr, nullptr, nullptr, nullptr,
                                            WH(7 + l), WL(7 + l), mlp_b2 + l * DD,
                                            pout, nullptr, NN, 0, 1, nullptr, nullptr);
        bn_apply_k<<<cdiv(NN * D4, TPB), TPB>>>(bn_gamma + l * DD, bn_beta + l * DD);
    }

    // ---- mean pool per graph + final projection
    pool_zero_k<<<cdiv(GG * DD, TPB), TPB>>>();
    pool_acc_k<<<cdiv(NN * D4, TPB), TPB>>>(batch);
    pool_cnt_k<<<cdiv(NN, TPB), TPB>>>(batch);
    pool_div_k<<<cdiv(GG * DD, TPB), TPB>>>();
    hgemm_k<0><<<grid_G, 256, SMEMSZ>>>(ppool, nullptr, nullptr, nullptr, nullptr,
                                        WH(12), WL(12), pool_b, out, nullptr, GG, 0, 0, nullptr, nullptr);
}

// round 7
// speedup vs baseline: 1.0768x; 1.0768x over previous
#include <cuda_runtime.h>
#include <cuda_bf16.h>
#include <cstdint>

#define NN 100000
#define EE 260000
#define DD 300
#define D4 75          // DD/4
#define LL 5
#define GG 4096
#define BN_EPS 1e-5f

// ---- HMMA GEMM geometry ----
#define BM   128
#define BNB  64
#define BKC  64
#define KPAD 320
#define NPAD 320
#define NCHK 5
#define NMAT 13

#define SA_H 0
#define SA_L 16384
#define SB_H 32768
#define SB_L 40960
#define STAGE 49152
#define SMEMSZ (2 * STAGE)   // 96 KB dynamic

// ---------------- scratch (device globals; no allocation allowed) ----------
__device__ __align__(16) float g_h  [(size_t)NN * DD];
__device__ __align__(16) float g_e  [(size_t)EE * DD];
__device__ __align__(16) float g_agg[(size_t)NN * DD];
__device__ __align__(16) float g_tmp[(size_t)EE * DD];   // edge tmp (N<=E) & layer tmp
__device__ __align__(16) float g_out[(size_t)NN * DD];
__device__             float g_stats[2 * DD];
__device__ __align__(16) float g_pool[(size_t)GG * DD];
__device__             float g_cnt [GG];
__device__ __align__(16) __nv_bfloat16 g_wbh[(size_t)NMAT * NPAD * KPAD];
__device__ __align__(16) __nv_bfloat16 g_wbl[(size_t)NMAT * NPAD * KPAD];

// ---------------- helpers ----------------------------------------------------
__device__ __forceinline__ uint32_t smem_u32(const void* p) {
    uint32_t a;
    asm("{ .reg .u64 t; cvta.to.shared.u64 t, %1; cvt.u32.u64 %0, t; }" : "=r"(a) : "l"(p));
    return a;
}
__device__ __forceinline__ uint32_t swz(uint32_t off) { return off ^ ((off >> 3) & 0x70); }

__device__ __forceinline__ void ldsm4(uint32_t* r, uint32_t addr) {
    asm volatile("ldmatrix.sync.aligned.m8n8.x4.shared.b16 {%0,%1,%2,%3}, [%4];"
                 : "=r"(r[0]), "=r"(r[1]), "=r"(r[2]), "=r"(r[3]) : "r"(addr));
}
__device__ __forceinline__ void mma_bf16(float* d, const uint32_t* a, const uint32_t* b) {
    asm volatile(
        "mma.sync.aligned.m16n8k16.row.col.f32.bf16.bf16.f32 "
        "{%0,%1,%2,%3}, {%4,%5,%6,%7}, {%8,%9}, {%0,%1,%2,%3};"
        : "+f"(d[0]), "+f"(d[1]), "+f"(d[2]), "+f"(d[3])
        : "r"(a[0]), "r"(a[1]), "r"(a[2]), "r"(a[3]), "r"(b[0]), "r"(b[1]));
}
__device__ __forceinline__ uint32_t pack_bf16(float a, float b) {
    __nv_bfloat16 ha = __float2bfloat16_rn(a), hb = __float2bfloat16_rn(b);
    return (uint32_t)__bfloat16_as_ushort(ha) | ((uint32_t)__bfloat16_as_ushort(hb) << 16);
}
__device__ __forceinline__ void red_add_v4(float* p, float4 v) {
    asm volatile("red.global.add.v4.f32 [%0], {%1, %2, %3, %4};"
                 :: "l"(p), "f"(v.x), "f"(v.y), "f"(v.z), "f"(v.w) : "memory");
}

// ---------------- weight preconversion ---------------------------------------
__global__ void wprep_k(const float* __restrict__ nap_w2, const float* __restrict__ ee_w2,
                        const float* __restrict__ mlp_w1, const float* __restrict__ mlp_w2,
                        const float* __restrict__ pool_w) {
    int idx = blockIdx.x * blockDim.x + threadIdx.x;
    if (idx >= NMAT * NPAD * KPAD) return;
    int mat = idx / (NPAD * KPAD);
    int rem = idx - mat * (NPAD * KPAD);
    int n = rem / KPAD, k = rem - n * KPAD;
    const float* W;
    if (mat == 0)      W = nap_w2;
    else if (mat == 1) W = ee_w2;
    else if (mat < 7)  W = mlp_w1 + (size_t)(mat - 2) * DD * DD;
    else if (mat < 12) W = mlp_w2 + (size_t)(mat - 7) * DD * DD;
    else               W = pool_w;
    float v = (n < DD && k < DD) ? W[(size_t)k * DD + n] : 0.f;
    __nv_bfloat16 hi = __float2bfloat16_rn(v);
    __nv_bfloat16 lo = __float2bfloat16_rn(v - __bfloat162float(hi));
    g_wbh[idx] = hi;
    g_wbl[idx] = lo;
}

// ---------------- HMMA GEMM (A from memory; optional BN-stats epilogue) ------
__global__ __launch_bounds__(256, 2)
void hgemm_k(const float* __restrict__ A,
             const __nv_bfloat16* __restrict__ Bh, const __nv_bfloat16* __restrict__ Bl,
             const float* __restrict__ bias, float* __restrict__ C,
             float* __restrict__ C2, int M, int relu, int stats,
             const float* __restrict__ gtab, const int* __restrict__ gidx) {
    extern __shared__ char smem[];
    __shared__ float sred[128];
    const uint32_t sb = smem_u32(smem);
    const int tid  = threadIdx.x;
    const int lane = tid & 31;
    const int wid  = tid >> 5;
    const int warpM = wid & 3;
    const int warpN = wid >> 2;
    const int m0 = blockIdx.y * BM;
    const int n0 = blockIdx.x * BNB;

    const int ar   = tid >> 1;
    const int half = tid & 1;
    const int gm_a = m0 + ar;

    auto fill = [&](int c, int s) {
        char* st = smem + (s ? STAGE : 0);
        {
            const float* arow = A + (size_t)gm_a * DD + c * BKC;
            #pragma unroll
            for (int i = 0; i < 8; i++) {
                const int kl = half * 32 + i * 4;
                const int k  = c * BKC + kl;
                float4 v = make_float4(0.f, 0.f, 0.f, 0.f);
                if (gm_a < M && k + 4 <= DD) v = *(const float4*)&arow[kl];
                float hx = __bfloat162float(__float2bfloat16_rn(v.x));
                float hy = __bfloat162float(__float2bfloat16_rn(v.y));
                float hz = __bfloat162float(__float2bfloat16_rn(v.z));
                float hw = __bfloat162float(__float2bfloat16_rn(v.w));
                uint32_t hA = pack_bf16(v.x, v.y), hB = pack_bf16(v.z, v.w);
                uint32_t lA = pack_bf16(v.x - hx, v.y - hy), lB = pack_bf16(v.z - hz, v.w - hw);
                const uint32_t so = swz(ar * 128 + kl * 2);
                *(uint2*)(st + SA_H + so) = make_uint2(hA, hB);
                *(uint2*)(st + SA_L + so) = make_uint2(lA, lB);
            }
        }
        {
            #pragma unroll
            for (int it = 0; it < 2; it++) {
                const int i = tid + it * 256;
                const int n = i >> 3, ku = i & 7;
                const size_t go = (size_t)(n0 + n) * KPAD + c * BKC + ku * 8;
                uint4 vh = *(const uint4*)(Bh + go);
                uint4 vl = *(const uint4*)(Bl + go);
                const uint32_t so = swz(n * 128 + ku * 16);
                *(uint4*)(st + SB_H + so) = vh;
                *(uint4*)(st + SB_L + so) = vl;
            }
        }
    };

    float acc[2][4][4] = {};

    const int a_row = lane & 15;
    const int a_kc  = (lane >> 4) * 8;
    const int b_row = (lane & 7) + ((lane & 16) ? 8 : 0);
    const int b_kc  = (lane & 8);

    fill(0, 0);
    __syncthreads();

    for (int c = 0; c < NCHK; c++) {
        const int s = c & 1;
        if (c + 1 < NCHK) fill(c + 1, s ^ 1);

        const uint32_t stb = sb + (s ? STAGE : 0);
        #pragma unroll
        for (int ks = 0; ks < 4; ks++) {
            const int k0 = ks * 16;
            uint32_t ah[2][4], al[2][4], bh[2][4], bl[2][4];
            #pragma unroll
            for (int mt = 0; mt < 2; mt++) {
                const uint32_t off = swz((warpM * 32 + mt * 16 + a_row) * 128 + (k0 + a_kc) * 2);
                ldsm4(ah[mt], stb + SA_H + off);
                ldsm4(al[mt], stb + SA_L + off);
            }
            #pragma unroll
            for (int g = 0; g < 2; g++) {
                const uint32_t off = swz((warpN * 32 + g * 16 + b_row) * 128 + (k0 + b_kc) * 2);
                ldsm4(bh[g], stb + SB_H + off);
                ldsm4(bl[g], stb + SB_L + off);
            }
            #pragma unroll
            for (int mt = 0; mt < 2; mt++) {
                #pragma unroll
                for (int nt = 0; nt < 4; nt++) {
                    const int g = nt >> 1, o = (nt & 1) * 2;
                    mma_bf16(acc[mt][nt], ah[mt], &bh[g][o]);
                    mma_bf16(acc[mt][nt], ah[mt], &bl[g][o]);
                    mma_bf16(acc[mt][nt], al[mt], &bh[g][o]);
                }
            }
        }
        __syncthreads();
    }

    // ---- epilogue
    const int er = lane >> 2;
    const int ec = (lane & 3) * 2;
    float cs[8] = {}, cq[8] = {};
    #pragma unroll
    for (int mt = 0; mt < 2; mt++) {
        #pragma unroll
        for (int rr = 0; rr < 2; rr++) {
            const int gm = m0 + warpM * 32 + mt * 16 + rr * 8 + er;
            if (gm < M) {
                const float* grow = (gtab != nullptr) ? gtab + (size_t)gidx[gm] * DD : nullptr;
                float* crow  = C + (size_t)gm * DD;
                float* c2row = (C2 != nullptr) ? C2 + (size_t)gm * DD : nullptr;
                #pragma unroll
                for (int nt = 0; nt < 4; nt++) {
                    const int n = n0 + warpN * 32 + nt * 8 + ec;
                    if (n + 2 <= DD) {
                        float v0 = acc[mt][nt][rr * 2 + 0] + bias[n];
                        float v1 = acc[mt][nt][rr * 2 + 1] + bias[n + 1];
                        if (grow != nullptr) { v0 += grow[n]; v1 += grow[n + 1]; }
                        if (relu) { v0 = fmaxf(v0, 0.f); v1 = fmaxf(v1, 0.f); }
                        *(float2*)&crow[n] = make_float2(v0, v1);
                        if (c2row != nullptr) *(float2*)&c2row[n] = make_float2(v0, v1);
                        if (stats) {
                            const int j = nt * 2;
                            cs[j] += v0; cq[j] += v0 * v0;
                            cs[j + 1] += v1; cq[j + 1] += v1 * v1;
                        }
                    }
                }
            }
        }
    }
    if (stats) {
        if (tid < 64) { sred[tid] = 0.f; sred[64 + tid] = 0.f; }
        __syncthreads();
        #pragma unroll
        for (int nt = 0; nt < 4; nt++) {
            const int col = warpN * 32 + nt * 8 + ec;
            atomicAdd(&sred[col],          cs[nt * 2]);
            atomicAdd(&sred[64 + col],     cq[nt * 2]);
            atomicAdd(&sred[col + 1],      cs[nt * 2 + 1]);
            atomicAdd(&sred[64 + col + 1], cq[nt * 2 + 1]);
        }
        __syncthreads();
        if (tid < 64) {
            const int n = n0 + tid;
            if (n < DD) {
                atomicAdd(&g_stats[n],      sred[tid]);
                atomicAdd(&g_stats[DD + n], sred[64 + tid]);
            }
        }
    }
}

// ---------------- elementwise preambles (float4 vectorized) ------------------
__global__ void node_pre_k(const float* __restrict__ chi, const float* __restrict__ fc,
                           const float* __restrict__ w1, const float* __restrict__ b1) {
    int idx = blockIdx.x * blockDim.x + threadIdx.x;
    if (idx >= NN * D4) return;
    int n = idx / D4, j = idx - n * D4;
    int d = j * 4;
    float c0 = chi[n], c1 = fc[n];
    float4 w0 = *(const float4*)&w1[d];
    float4 w1r = *(const float4*)&w1[DD + d];
    float4 b  = *(const float4*)&b1[d];
    float4 v;
    v.x = fmaxf(c0 * w0.x + c1 * w1r.x + b.x, 0.f);
    v.y = fmaxf(c0 * w0.y + c1 * w1r.y + b.y, 0.f);
    v.z = fmaxf(c0 * w0.z + c1 * w1r.z + b.z, 0.f);
    v.w = fmaxf(c0 * w0.w + c1 * w1r.w + b.w, 0.f);
    reinterpret_cast<float4*>(g_tmp)[idx] = v;
}

__global__ void edge_pre_k(const float* __restrict__ ea,
                           const float* __restrict__ w1, const float* __restrict__ b1) {
    int idx = blockIdx.x * blockDim.x + threadIdx.x;
    if (idx >= EE * D4) return;
    int e = idx / D4, j = idx - e * D4;
    int d = j * 4;
    float c0 = ea[e * 3 + 0], c1 = ea[e * 3 + 1], c2 = ea[e * 3 + 2];
    float4 w0 = *(const float4*)&w1[d];
    float4 w1r = *(const float4*)&w1[DD + d];
    float4 w2r = *(const float4*)&w1[2 * DD + d];
    float4 b  = *(const float4*)&b1[d];
    float4 v;
    v.x = fmaxf(c0 * w0.x + c1 * w1r.x + c2 * w2r.x + b.x, 0.f);
    v.y = fmaxf(c0 * w0.y + c1 * w1r.y + c2 * w2r.y + b.y, 0.f);
    v.z = fmaxf(c0 * w0.z + c1 * w1r.z + c2 * w2r.z + b.z, 0.f);
    v.w = fmaxf(c0 * w0.w + c1 * w1r.w + c2 * w2r.w + b.w, 0.f);
    reinterpret_cast<float4*>(g_tmp)[idx] = v;
}

// ---------------- message + scatter-add (vector red, agg preseeded with h) --
__global__ void msg_k(const int* __restrict__ ei) {
    int idx = blockIdx.x * blockDim.x + threadIdx.x;
    if (idx >= EE * D4) return;
    int e = idx / D4, j = idx - e * D4;
    int s = __ldg(&ei[e]);
    int d = __ldg(&ei[EE + e]);
    float4 hv = reinterpret_cast<const float4*>(g_h)[(size_t)s * D4 + j];
    float4 ev = reinterpret_cast<const float4*>(g_e)[(size_t)e * D4 + j];
    float4 x;
    x.x = fmaxf(hv.x + ev.x, 0.f);
    x.y = fmaxf(hv.y + ev.y, 0.f);
    x.z = fmaxf(hv.z + ev.z, 0.f);
    x.w = fmaxf(hv.w + ev.w, 0.f);
    red_add_v4(&g_agg[(size_t)d * DD + j * 4], x);
}

// ---------------- batchnorm --------------------------------------------------
__global__ void zero_stats_k() {
    int i = threadIdx.x;
    if (i < 2 * DD) g_stats[i] = 0.f;
}

__global__ void bn_apply_k(const float* __restrict__ gamma, const float* __restrict__ beta) {
    int idx = blockIdx.x * blockDim.x + threadIdx.x;
    if (idx >= NN * D4) return;
    int j = idx % D4;
    int d = j * 4;
    const float invN = 1.f / (float)NN;
    float4 mu = make_float4(g_stats[d] * invN, g_stats[d + 1] * invN,
                            g_stats[d + 2] * invN, g_stats[d + 3] * invN);
    float4 ms = make_float4(g_stats[DD + d] * invN, g_stats[DD + d + 1] * invN,
                            g_stats[DD + d + 2] * invN, g_stats[DD + d + 3] * invN);
    float4 ga = *(const float4*)&gamma[d];
    float4 be = *(const float4*)&beta[d];
    float4 o = reinterpret_cast<const float4*>(g_out)[idx];
    float4 v;
    v.x = fmaxf(ga.x * (o.x - mu.x) * rsqrtf(ms.x - mu.x * mu.x + BN_EPS) + be.x, 0.f);
    v.y = fmaxf(ga.y * (o.y - mu.y) * rsqrtf(ms.y - mu.y * mu.y + BN_EPS) + be.y, 0.f);
    v.z = fmaxf(ga.z * (o.z - mu.z) * rsqrtf(ms.z - mu.z * mu.z + BN_EPS) + be.z, 0.f);
    v.w = fmaxf(ga.w * (o.w - mu.w) * rsqrtf(ms.w - mu.w * mu.w + BN_EPS) + be.w, 0.f);
    reinterpret_cast<float4*>(g_h)[idx]   = v;
    reinterpret_cast<float4*>(g_agg)[idx] = v;   // pre-seed next layer aggregate
}

// ---------------- pooling ----------------------------------------------------
__global__ void pool_zero_k() {
    int idx = blockIdx.x * blockDim.x + threadIdx.x;
    if (idx < GG * DD) g_pool[idx] = 0.f;
    if (idx < GG) g_cnt[idx] = 0.f;
}

__global__ void pool_acc_k(const int* __restrict__ batch) {
    int idx = blockIdx.x * blockDim.x + threadIdx.x;
    if (idx >= NN * D4) return;
    int n = idx / D4, j = idx - n * D4;
    int g = __ldg(&batch[n]);
    float4 v = reinterpret_cast<const float4*>(g_h)[(size_t)n * D4 + j];
    red_add_v4(&g_pool[(size_t)g * DD + j * 4], v);
}

__global__ void pool_cnt_k(const int* __restrict__ batch) {
    int n = blockIdx.x * blockDim.x + threadIdx.x;
    if (n >= NN) return;
    atomicAdd(&g_cnt[batch[n]], 1.f);
}

__global__ void pool_div_k() {
    int idx = blockIdx.x * blockDim.x + threadIdx.x;
    if (idx >= GG * DD) return;
    int g = idx / DD;
    float c = g_cnt[g];
    g_pool[idx] = (c > 0.f) ? g_pool[idx] / c : 0.f;
}

// ---------------- launch -----------------------------------------------------
static inline int cdiv(int a, int b) { return (a + b - 1) / b; }

extern "C" void kernel_launch(void* const* d_in, const int* in_sizes, int n_in,
                              void* d_out, int out_size) {
    const int*   z        = (const int*)  d_in[0];
    const float* chi      = (const float*)d_in[1];
    const float* fc       = (const float*)d_in[2];
    const int*   ei       = (const int*)  d_in[3];
    const float* ea       = (const float*)d_in[4];
    const int*   batch    = (const int*)  d_in[5];
    const float* atom_emb = (const float*)d_in[6];
    const float* nap_w1   = (const float*)d_in[7];
    const float* nap_b1   = (const float*)d_in[8];
    const float* nap_w2   = (const float*)d_in[9];
    const float* nap_b2   = (const float*)d_in[10];
    const float* ee_w1    = (const float*)d_in[11];
    const float* ee_b1    = (const float*)d_in[12];
    const float* ee_w2    = (const float*)d_in[13];
    const float* ee_b2    = (const float*)d_in[14];
    const float* mlp_w1   = (const float*)d_in[15];
    const float* mlp_b1   = (const float*)d_in[16];
    const float* mlp_w2   = (const float*)d_in[17];
    const float* mlp_b2   = (const float*)d_in[18];
    const float* bn_gamma = (const float*)d_in[19];
    const float* bn_beta  = (const float*)d_in[20];
    const float* pool_w   = (const float*)d_in[21];
    const float* pool_b   = (const float*)d_in[22];
    float* out = (float*)d_out;

    float *ph, *pe, *pagg, *ptmp, *pout, *ppool;
    __nv_bfloat16 *pwh, *pwl;
    cudaGetSymbolAddress((void**)&ph,    g_h);
    cudaGetSymbolAddress((void**)&pe,    g_e);
    cudaGetSymbolAddress((void**)&pagg,  g_agg);
    cudaGetSymbolAddress((void**)&ptmp,  g_tmp);
    cudaGetSymbolAddress((void**)&pout,  g_out);
    cudaGetSymbolAddress((void**)&ppool, g_pool);
    cudaGetSymbolAddress((void**)&pwh,   g_wbh);
    cudaGetSymbolAddress((void**)&pwl,   g_wbl);

    cudaFuncSetAttribute(hgemm_k, cudaFuncAttributeMaxDynamicSharedMemorySize, SMEMSZ);

    const int TPB = 256;
    const size_t WSTRIDE = (size_t)NPAD * KPAD;
    #define WH(m) (pwh + (size_t)(m) * WSTRIDE)
    #define WL(m) (pwl + (size_t)(m) * WSTRIDE)

    dim3 grid_N(NPAD / BNB, cdiv(NN, BM));
    dim3 grid_E(NPAD / BNB, cdiv(EE, BM));
    dim3 grid_G(NPAD / BNB, cdiv(GG, BM));

    // ---- preconvert all weight matrices to bf16 hi/lo (K-major, padded)
    wprep_k<<<cdiv(NMAT * NPAD * KPAD, TPB), TPB>>>(nap_w2, ee_w2, mlp_w1, mlp_w2, pool_w);

    // ---- node features: h0 = atom_emb[z] + MLP(node_attr); seed agg = h0
    node_pre_k<<<cdiv(NN * D4, TPB), TPB>>>(chi, fc, nap_w1, nap_b1);
    hgemm_k<<<grid_N, 256, SMEMSZ>>>(ptmp, WH(0), WL(0), nap_b2, ph, pagg, NN, 0, 0, atom_emb, z);

    // ---- edge features: e = MLP(edge_attr)
    edge_pre_k<<<cdiv(EE * D4, TPB), TPB>>>(ea, ee_w1, ee_b1);
    hgemm_k<<<grid_E, 256, SMEMSZ>>>(ptmp, WH(1), WL(1), ee_b2, pe, nullptr, EE, 0, 0, nullptr, nullptr);

    // ---- L GINE layers
    for (int l = 0; l < LL; l++) {
        msg_k<<<cdiv(EE * D4, TPB), TPB>>>(ei);
        hgemm_k<<<grid_N, 256, SMEMSZ>>>(pagg, WH(2 + l), WL(2 + l), mlp_b1 + l * DD,
                                         ptmp, nullptr, NN, 1, 0, nullptr, nullptr);
        zero_stats_k<<<1, 2 * DD>>>();
        hgemm_k<<<grid_N, 256, SMEMSZ>>>(ptmp, WH(7 + l), WL(7 + l), mlp_b2 + l * DD,
                                         pout, nullptr, NN, 0, 1, nullptr, nullptr);
        bn_apply_k<<<cdiv(NN * D4, TPB), TPB>>>(bn_gamma + l * DD, bn_beta + l * DD);
    }

    // ---- mean pool per graph + final projection
    pool_zero_k<<<cdiv(GG * DD, TPB), TPB>>>();
    pool_acc_k<<<cdiv(NN * D4, TPB), TPB>>>(batch);
    pool_cnt_k<<<cdiv(NN, TPB), TPB>>>(batch);
    pool_div_k<<<cdiv(GG * DD, TPB), TPB>>>();
    hgemm_k<<<grid_G, 256, SMEMSZ>>>(ppool, WH(12), WL(12), pool_b, out, nullptr, GG, 0, 0, nullptr, nullptr);
}

// round 8
// speedup vs baseline: 1.1240x; 1.0438x over previous
#include <cuda_runtime.h>
#include <cuda_bf16.h>
#include <cuda_fp16.h>
#include <cstdint>

#define NN 100000
#define EE 260000
#define DD 300
#define D4 75          // DD/4
#define LL 5
#define GG 4096
#define BN_EPS 1e-5f

// ---- HMMA GEMM geometry ----
#define BM   128
#define BNB  64
#define BKC  64
#define KPAD 320
#define NPAD 320
#define NCHK 5
#define NMAT 13

#define SA_H 0
#define SA_L 16384
#define SB_H 32768
#define SB_L 40960
#define STAGE 49152
#define SMEMSZ (2 * STAGE)   // 96 KB dynamic

// ---------------- scratch (device globals; no allocation allowed) ----------
__device__ __align__(16) float  g_h   [(size_t)NN * DD];
__device__ __align__(16) __half g_eh  [(size_t)EE * DD];   // edge features (fp16)
__device__ __align__(16) __half g_tmph[(size_t)EE * DD];   // edge pre-projection (fp16)
__device__ __align__(16) float  g_agg [(size_t)NN * DD];
__device__ __align__(16) float  g_tmp [(size_t)NN * DD];   // node layer intermediate
__device__ __align__(16) float  g_out [(size_t)NN * DD];   // node pre-proj & mlp2 out
__device__              float  g_stats[2 * DD];
__device__ __align__(16) float  g_pool[(size_t)GG * DD];
__device__              float  g_cnt [GG];
__device__ __align__(16) __nv_bfloat16 g_wbh[(size_t)NMAT * NPAD * KPAD];
__device__ __align__(16) __nv_bfloat16 g_wbl[(size_t)NMAT * NPAD * KPAD];

// ---------------- helpers ----------------------------------------------------
__device__ __forceinline__ uint32_t smem_u32(const void* p) {
    uint32_t a;
    asm("{ .reg .u64 t; cvta.to.shared.u64 t, %1; cvt.u32.u64 %0, t; }" : "=r"(a) : "l"(p));
    return a;
}
__device__ __forceinline__ uint32_t swz(uint32_t off) { return off ^ ((off >> 3) & 0x70); }

__device__ __forceinline__ void ldsm4(uint32_t* r, uint32_t addr) {
    asm volatile("ldmatrix.sync.aligned.m8n8.x4.shared.b16 {%0,%1,%2,%3}, [%4];"
                 : "=r"(r[0]), "=r"(r[1]), "=r"(r[2]), "=r"(r[3]) : "r"(addr));
}
__device__ __forceinline__ void mma_bf16(float* d, const uint32_t* a, const uint32_t* b) {
    asm volatile(
        "mma.sync.aligned.m16n8k16.row.col.f32.bf16.bf16.f32 "
        "{%0,%1,%2,%3}, {%4,%5,%6,%7}, {%8,%9}, {%0,%1,%2,%3};"
        : "+f"(d[0]), "+f"(d[1]), "+f"(d[2]), "+f"(d[3])
        : "r"(a[0]), "r"(a[1]), "r"(a[2]), "r"(a[3]), "r"(b[0]), "r"(b[1]));
}
__device__ __forceinline__ uint32_t pack_bf16(float a, float b) {
    __nv_bfloat16 ha = __float2bfloat16_rn(a), hb = __float2bfloat16_rn(b);
    return (uint32_t)__bfloat16_as_ushort(ha) | ((uint32_t)__bfloat16_as_ushort(hb) << 16);
}
__device__ __forceinline__ void red_add_v4(float* p, float4 v) {
    asm volatile("red.global.add.v4.f32 [%0], {%1, %2, %3, %4};"
                 :: "l"(p), "f"(v.x), "f"(v.y), "f"(v.z), "f"(v.w) : "memory");
}

// ---------------- weight preconversion ---------------------------------------
__global__ void wprep_k(const float* __restrict__ nap_w2, const float* __restrict__ ee_w2,
                        const float* __restrict__ mlp_w1, const float* __restrict__ mlp_w2,
                        const float* __restrict__ pool_w) {
    int idx = blockIdx.x * blockDim.x + threadIdx.x;
    if (idx >= NMAT * NPAD * KPAD) return;
    int mat = idx / (NPAD * KPAD);
    int rem = idx - mat * (NPAD * KPAD);
    int n = rem / KPAD, k = rem - n * KPAD;
    const float* W;
    if (mat == 0)      W = nap_w2;
    else if (mat == 1) W = ee_w2;
    else if (mat < 7)  W = mlp_w1 + (size_t)(mat - 2) * DD * DD;
    else if (mat < 12) W = mlp_w2 + (size_t)(mat - 7) * DD * DD;
    else               W = pool_w;
    float v = (n < DD && k < DD) ? W[(size_t)k * DD + n] : 0.f;
    __nv_bfloat16 hi = __float2bfloat16_rn(v);
    __nv_bfloat16 lo = __float2bfloat16_rn(v - __bfloat162float(hi));
    g_wbh[idx] = hi;
    g_wbl[idx] = lo;
}

// ---------------- HMMA GEMM --------------------------------------------------
// AM: 0 = A fp32, 1 = A fp16.   CM: 0 = C fp32 (+C2/gather/stats), 1 = C fp16.
template<int AM, int CM>
__global__ __launch_bounds__(256, 2)
void hgemm_k(const void* __restrict__ Av,
             const __nv_bfloat16* __restrict__ Bh, const __nv_bfloat16* __restrict__ Bl,
             const float* __restrict__ bias, float* __restrict__ C,
             float* __restrict__ C2, __half* __restrict__ Ce, int M, int relu, int stats,
             const float* __restrict__ gtab, const int* __restrict__ gidx) {
    extern __shared__ char smem[];
    __shared__ float sred[128];
    const uint32_t sb = smem_u32(smem);
    const int tid  = threadIdx.x;
    const int lane = tid & 31;
    const int wid  = tid >> 5;
    const int warpM = wid & 3;
    const int warpN = wid >> 2;
    const int m0 = blockIdx.y * BM;
    const int n0 = blockIdx.x * BNB;

    const int ar   = tid >> 1;
    const int half = tid & 1;
    const int gm_a = m0 + ar;

    auto fill = [&](int c, int s) {
        char* st = smem + (s ? STAGE : 0);
        {
            #pragma unroll
            for (int i = 0; i < 8; i++) {
                const int kl = half * 32 + i * 4;
                const int k  = c * BKC + kl;
                float4 v = make_float4(0.f, 0.f, 0.f, 0.f);
                if (gm_a < M && k + 4 <= DD) {
                    if constexpr (AM == 0) {
                        v = *(const float4*)((const float*)Av + (size_t)gm_a * DD + k);
                    } else {
                        uint2 u = *(const uint2*)((const __half*)Av + (size_t)gm_a * DD + k);
                        __half2 h01 = *reinterpret_cast<__half2*>(&u.x);
                        __half2 h23 = *reinterpret_cast<__half2*>(&u.y);
                        float2 f01 = __half22float2(h01), f23 = __half22float2(h23);
                        v = make_float4(f01.x, f01.y, f23.x, f23.y);
                    }
                }
                float hx = __bfloat162float(__float2bfloat16_rn(v.x));
                float hy = __bfloat162float(__float2bfloat16_rn(v.y));
                float hz = __bfloat162float(__float2bfloat16_rn(v.z));
                float hw = __bfloat162float(__float2bfloat16_rn(v.w));
                uint32_t hA = pack_bf16(v.x, v.y), hB = pack_bf16(v.z, v.w);
                uint32_t lA = pack_bf16(v.x - hx, v.y - hy), lB = pack_bf16(v.z - hz, v.w - hw);
                const uint32_t so = swz(ar * 128 + kl * 2);
                *(uint2*)(st + SA_H + so) = make_uint2(hA, hB);
                *(uint2*)(st + SA_L + so) = make_uint2(lA, lB);
            }
        }
        {
            #pragma unroll
            for (int it = 0; it < 2; it++) {
                const int i = tid + it * 256;
                const int n = i >> 3, ku = i & 7;
                const size_t go = (size_t)(n0 + n) * KPAD + c * BKC + ku * 8;
                uint4 vh = *(const uint4*)(Bh + go);
                uint4 vl = *(const uint4*)(Bl + go);
                const uint32_t so = swz(n * 128 + ku * 16);
                *(uint4*)(st + SB_H + so) = vh;
                *(uint4*)(st + SB_L + so) = vl;
            }
        }
    };

    float acc[2][4][4] = {};

    const int a_row = lane & 15;
    const int a_kc  = (lane >> 4) * 8;
    const int b_row = (lane & 7) + ((lane & 16) ? 8 : 0);
    const int b_kc  = (lane & 8);

    fill(0, 0);
    __syncthreads();

    for (int c = 0; c < NCHK; c++) {
        const int s = c & 1;
        if (c + 1 < NCHK) fill(c + 1, s ^ 1);

        const uint32_t stb = sb + (s ? STAGE : 0);
        #pragma unroll
        for (int ks = 0; ks < 4; ks++) {
            const int k0 = ks * 16;
            uint32_t ah[2][4], al[2][4], bh[2][4], bl[2][4];
            #pragma unroll
            for (int mt = 0; mt < 2; mt++) {
                const uint32_t off = swz((warpM * 32 + mt * 16 + a_row) * 128 + (k0 + a_kc) * 2);
                ldsm4(ah[mt], stb + SA_H + off);
                ldsm4(al[mt], stb + SA_L + off);
            }
            #pragma unroll
            for (int g = 0; g < 2; g++) {
                const uint32_t off = swz((warpN * 32 + g * 16 + b_row) * 128 + (k0 + b_kc) * 2);
                ldsm4(bh[g], stb + SB_H + off);
                ldsm4(bl[g], stb + SB_L + off);
            }
            #pragma unroll
            for (int mt = 0; mt < 2; mt++) {
                #pragma unroll
                for (int nt = 0; nt < 4; nt++) {
                    const int g = nt >> 1, o = (nt & 1) * 2;
                    mma_bf16(acc[mt][nt], ah[mt], &bh[g][o]);
                    mma_bf16(acc[mt][nt], ah[mt], &bl[g][o]);
                    mma_bf16(acc[mt][nt], al[mt], &bh[g][o]);
                }
            }
        }
        __syncthreads();
    }

    // ---- epilogue
    const int er = lane >> 2;
    const int ec = (lane & 3) * 2;
    float cs[8] = {}, cq[8] = {};
    #pragma unroll
    for (int mt = 0; mt < 2; mt++) {
        #pragma unroll
        for (int rr = 0; rr < 2; rr++) {
            const int gm = m0 + warpM * 32 + mt * 16 + rr * 8 + er;
            if (gm < M) {
                const float* grow = (CM == 0 && gtab != nullptr) ? gtab + (size_t)gidx[gm] * DD : nullptr;
                #pragma unroll
                for (int nt = 0; nt < 4; nt++) {
                    const int n = n0 + warpN * 32 + nt * 8 + ec;
                    if (n + 2 <= DD) {
                        float v0 = acc[mt][nt][rr * 2 + 0] + bias[n];
                        float v1 = acc[mt][nt][rr * 2 + 1] + bias[n + 1];
                        if (grow != nullptr) { v0 += grow[n]; v1 += grow[n + 1]; }
                        if (relu) { v0 = fmaxf(v0, 0.f); v1 = fmaxf(v1, 0.f); }
                        if constexpr (CM == 0) {
                            float* crow = C + (size_t)gm * DD;
                            *(float2*)&crow[n] = make_float2(v0, v1);
                            if (C2 != nullptr)
                                *(float2*)&(C2 + (size_t)gm * DD)[n] = make_float2(v0, v1);
                        } else {
                            *(__half2*)&(Ce + (size_t)gm * DD)[n] = __floats2half2_rn(v0, v1);
                        }
                        if (stats) {
                            const int j = nt * 2;
                            cs[j] += v0; cq[j] += v0 * v0;
                            cs[j + 1] += v1; cq[j + 1] += v1 * v1;
                        }
                    }
                }
            }
        }
    }
    if (stats) {
        if (tid < 64) { sred[tid] = 0.f; sred[64 + tid] = 0.f; }
        __syncthreads();
        #pragma unroll
        for (int nt = 0; nt < 4; nt++) {
            const int col = warpN * 32 + nt * 8 + ec;
            atomicAdd(&sred[col],          cs[nt * 2]);
            atomicAdd(&sred[64 + col],     cq[nt * 2]);
            atomicAdd(&sred[col + 1],      cs[nt * 2 + 1]);
            atomicAdd(&sred[64 + col + 1], cq[nt * 2 + 1]);
        }
        __syncthreads();
        if (tid < 64) {
            const int n = n0 + tid;
            if (n < DD) {
                atomicAdd(&g_stats[n],      sred[tid]);
                atomicAdd(&g_stats[DD + n], sred[64 + tid]);
            }
        }
    }
}

// ---------------- elementwise preambles --------------------------------------
__global__ void node_pre_k(const float* __restrict__ chi, const float* __restrict__ fc,
                           const float* __restrict__ w1, const float* __restrict__ b1) {
    int idx = blockIdx.x * blockDim.x + threadIdx.x;
    if (idx >= NN * D4) return;
    int n = idx / D4, j = idx - n * D4;
    int d = j * 4;
    float c0 = chi[n], c1 = fc[n];
    float4 w0 = *(const float4*)&w1[d];
    float4 w1r = *(const float4*)&w1[DD + d];
    float4 b  = *(const float4*)&b1[d];
    float4 v;
    v.x = fmaxf(c0 * w0.x + c1 * w1r.x + b.x, 0.f);
    v.y = fmaxf(c0 * w0.y + c1 * w1r.y + b.y, 0.f);
    v.z = fmaxf(c0 * w0.z + c1 * w1r.z + b.z, 0.f);
    v.w = fmaxf(c0 * w0.w + c1 * w1r.w + b.w, 0.f);
    reinterpret_cast<float4*>(g_out)[idx] = v;
}

__global__ void edge_pre_k(const float* __restrict__ ea,
                           const float* __restrict__ w1, const float* __restrict__ b1) {
    int idx = blockIdx.x * blockDim.x + threadIdx.x;
    if (idx >= EE * D4) return;
    int e = idx / D4, j = idx - e * D4;
    int d = j * 4;
    float c0 = ea[e * 3 + 0], c1 = ea[e * 3 + 1], c2 = ea[e * 3 + 2];
    float4 w0 = *(const float4*)&w1[d];
    float4 w1r = *(const float4*)&w1[DD + d];
    float4 w2r = *(const float4*)&w1[2 * DD + d];
    float4 b  = *(const float4*)&b1[d];
    float v0 = fmaxf(c0 * w0.x + c1 * w1r.x + c2 * w2r.x + b.x, 0.f);
    float v1 = fmaxf(c0 * w0.y + c1 * w1r.y + c2 * w2r.y + b.y, 0.f);
    float v2 = fmaxf(c0 * w0.z + c1 * w1r.z + c2 * w2r.z + b.z, 0.f);
    float v3 = fmaxf(c0 * w0.w + c1 * w1r.w + c2 * w2r.w + b.w, 0.f);
    uint2 u;
    *reinterpret_cast<__half2*>(&u.x) = __floats2half2_rn(v0, v1);
    *reinterpret_cast<__half2*>(&u.y) = __floats2half2_rn(v2, v3);
    reinterpret_cast<uint2*>(g_tmph)[idx] = u;
}

// ---------------- message + scatter-add (vector red, agg preseeded with h) --
__global__ void msg_k(const int* __restrict__ ei) {
    int idx = blockIdx.x * blockDim.x + threadIdx.x;
    if (idx >= EE * D4) return;
    int e = idx / D4, j = idx - e * D4;
    int s = __ldg(&ei[e]);
    int d = __ldg(&ei[EE + e]);
    float4 hv = reinterpret_cast<const float4*>(g_h)[(size_t)s * D4 + j];
    uint2 u = *(const uint2*)(g_eh + (size_t)e * DD + j * 4);
    float2 e01 = __half22float2(*reinterpret_cast<__half2*>(&u.x));
    float2 e23 = __half22float2(*reinterpret_cast<__half2*>(&u.y));
    float4 x;
    x.x = fmaxf(hv.x + e01.x, 0.f);
    x.y = fmaxf(hv.y + e01.y, 0.f);
    x.z = fmaxf(hv.z + e23.x, 0.f);
    x.w = fmaxf(hv.w + e23.y, 0.f);
    red_add_v4(&g_agg[(size_t)d * DD + j * 4], x);
}

// ---------------- batchnorm --------------------------------------------------
__global__ void zero_stats_k() {
    int i = threadIdx.x;
    if (i < 2 * DD) g_stats[i] = 0.f;
}

__global__ void bn_apply_k(const float* __restrict__ gamma, const float* __restrict__ beta) {
    int idx = blockIdx.x * blockDim.x + threadIdx.x;
    if (idx >= NN * D4) return;
    int j = idx % D4;
    int d = j * 4;
    const float invN = 1.f / (float)NN;
    float4 mu = make_float4(g_stats[d] * invN, g_stats[d + 1] * invN,
                            g_stats[d + 2] * invN, g_stats[d + 3] * invN);
    float4 ms = make_float4(g_stats[DD + d] * invN, g_stats[DD + d + 1] * invN,
                            g_stats[DD + d + 2] * invN, g_stats[DD + d + 3] * invN);
    float4 ga = *(const float4*)&gamma[d];
    float4 be = *(const float4*)&beta[d];
    float4 o = reinterpret_cast<const float4*>(g_out)[idx];
    float4 v;
    v.x = fmaxf(ga.x * (o.x - mu.x) * rsqrtf(ms.x - mu.x * mu.x + BN_EPS) + be.x, 0.f);
    v.y = fmaxf(ga.y * (o.y - mu.y) * rsqrtf(ms.y - mu.y * mu.y + BN_EPS) + be.y, 0.f);
    v.z = fmaxf(ga.z * (o.z - mu.z) * rsqrtf(ms.z - mu.z * mu.z + BN_EPS) + be.z, 0.f);
    v.w = fmaxf(ga.w * (o.w - mu.w) * rsqrtf(ms.w - mu.w * mu.w + BN_EPS) + be.w, 0.f);
    reinterpret_cast<float4*>(g_h)[idx]   = v;
    reinterpret_cast<float4*>(g_agg)[idx] = v;
}

// ---------------- pooling ----------------------------------------------------
__global__ void pool_zero_k() {
    int idx = blockIdx.x * blockDim.x + threadIdx.x;
    if (idx < GG * DD) g_pool[idx] = 0.f;
    if (idx < GG) g_cnt[idx] = 0.f;
}

__global__ void pool_acc_k(const int* __restrict__ batch) {
    int idx = blockIdx.x * blockDim.x + threadIdx.x;
    if (idx >= NN * D4) return;
    int n = idx / D4, j = idx - n * D4;
    int g = __ldg(&batch[n]);
    float4 v = reinterpret_cast<const float4*>(g_h)[(size_t)n * D4 + j];
    red_add_v4(&g_pool[(size_t)g * DD + j * 4], v);
    if (j == 0) atomicAdd(&g_cnt[g], 1.f);
}

__global__ void pool_div_k() {
    int idx = blockIdx.x * blockDim.x + threadIdx.x;
    if (idx >= GG * DD) return;
    int g = idx / DD;
    float c = g_cnt[g];
    g_pool[idx] = (c > 0.f) ? g_pool[idx] / c : 0.f;
}

// ---------------- launch -----------------------------------------------------
static inline int cdiv(int a, int b) { return (a + b - 1) / b; }

extern "C" void kernel_launch(void* const* d_in, const int* in_sizes, int n_in,
                              void* d_out, int out_size) {
    const int*   z        = (const int*)  d_in[0];
    const float* chi      = (const float*)d_in[1];
    const float* fc       = (const float*)d_in[2];
    const int*   ei       = (const int*)  d_in[3];
    const float* ea       = (const float*)d_in[4];
    const int*   batch    = (const int*)  d_in[5];
    const float* atom_emb = (const float*)d_in[6];
    const float* nap_w1   = (const float*)d_in[7];
    const float* nap_b1   = (const float*)d_in[8];
    const float* nap_w2   = (const float*)d_in[9];
    const float* nap_b2   = (const float*)d_in[10];
    const float* ee_w1    = (const float*)d_in[11];
    const float* ee_b1    = (const float*)d_in[12];
    const float* ee_w2    = (const float*)d_in[13];
    const float* ee_b2    = (const float*)d_in[14];
    const float* mlp_w1   = (const float*)d_in[15];
    const float* mlp_b1   = (const float*)d_in[16];
    const float* mlp_w2   = (const float*)d_in[17];
    const float* mlp_b2   = (const float*)d_in[18];
    const float* bn_gamma = (const float*)d_in[19];
    const float* bn_beta  = (const float*)d_in[20];
    const float* pool_w   = (const float*)d_in[21];
    const float* pool_b   = (const float*)d_in[22];
    float* out = (float*)d_out;

    float *ph, *pagg, *ptmp, *pout, *ppool;
    __half *peh, *ptmph;
    __nv_bfloat16 *pwh, *pwl;
    cudaGetSymbolAddress((void**)&ph,    g_h);
    cudaGetSymbolAddress((void**)&peh,   g_eh);
    cudaGetSymbolAddress((void**)&ptmph, g_tmph);
    cudaGetSymbolAddress((void**)&pagg,  g_agg);
    cudaGetSymbolAddress((void**)&ptmp,  g_tmp);
    cudaGetSymbolAddress((void**)&pout,  g_out);
    cudaGetSymbolAddress((void**)&ppool, g_pool);
    cudaGetSymbolAddress((void**)&pwh,   g_wbh);
    cudaGetSymbolAddress((void**)&pwl,   g_wbl);

    cudaFuncSetAttribute(hgemm_k<0,0>, cudaFuncAttributeMaxDynamicSharedMemorySize, SMEMSZ);
    cudaFuncSetAttribute(hgemm_k<1,1>, cudaFuncAttributeMaxDynamicSharedMemorySize, SMEMSZ);

    const int TPB = 256;
    const size_t WSTRIDE = (size_t)NPAD * KPAD;
    #define WH(m) (pwh + (size_t)(m) * WSTRIDE)
    #define WL(m) (pwl + (size_t)(m) * WSTRIDE)

    dim3 grid_N(NPAD / BNB, cdiv(NN, BM));
    dim3 grid_E(NPAD / BNB, cdiv(EE, BM));
    dim3 grid_G(NPAD / BNB, cdiv(GG, BM));

    // 0: weight preconversion
    wprep_k<<<cdiv(NMAT * NPAD * KPAD, TPB), TPB>>>(nap_w2, ee_w2, mlp_w1, mlp_w2, pool_w);
    // 1: edge pre-projection (fp16 out)
    edge_pre_k<<<cdiv(EE * D4, TPB), TPB>>>(ea, ee_w1, ee_b1);
    // 2: node pre-projection (fp32 out -> g_out)
    node_pre_k<<<cdiv(NN * D4, TPB), TPB>>>(chi, fc, nap_w1, nap_b1);
    // 3: h0 GEMM (node) — lands in ncu capture slot
    hgemm_k<0,0><<<grid_N, 256, SMEMSZ>>>(pout, WH(0), WL(0), nap_b2, ph, pagg, nullptr,
                                          NN, 0, 0, atom_emb, z);
    // 4: edge GEMM (fp16 A, fp16 C)
    hgemm_k<1,1><<<grid_E, 256, SMEMSZ>>>(ptmph, WH(1), WL(1), ee_b2, nullptr, nullptr, peh,
                                          EE, 0, 0, nullptr, nullptr);

    // ---- L GINE layers
    for (int l = 0; l < LL; l++) {
        msg_k<<<cdiv(EE * D4, TPB), TPB>>>(ei);
        hgemm_k<0,0><<<grid_N, 256, SMEMSZ>>>(pagg, WH(2 + l), WL(2 + l), mlp_b1 + l * DD,
                                              ptmp, nullptr, nullptr, NN, 1, 0, nullptr, nullptr);
        zero_stats_k<<<1, 2 * DD>>>();
        hgemm_k<0,0><<<grid_N, 256, SMEMSZ>>>(ptmp, WH(7 + l), WL(7 + l), mlp_b2 + l * DD,
                                              pout, nullptr, nullptr, NN, 0, 1, nullptr, nullptr);
        bn_apply_k<<<cdiv(NN * D4, TPB), TPB>>>(bn_gamma + l * DD, bn_beta + l * DD);
    }

    // ---- mean pool per graph + final projection
    pool_zero_k<<<cdiv(GG * DD, TPB), TPB>>>();
    pool_acc_k<<<cdiv(NN * D4, TPB), TPB>>>(batch);
    pool_div_k<<<cdiv(GG * DD, TPB), TPB>>>();
    hgemm_k<0,0><<<grid_G, 256, SMEMSZ>>>(ppool, WH(12), WL(12), pool_b, out, nullptr, nullptr,
                                          GG, 0, 0, nullptr, nullptr);
}